// round 3
// baseline (speedup 1.0000x reference)
#include <cuda_runtime.h>
#include <cstddef>

// in1,in2: [B=2, C=32, D=32, H=32, W=32] fp32
// out:     [B, 7,7,7, D, H, W] fp32
// out[b,od,oh,ow,d,h,w] = sum_c in1[b,c,d,h,w]*in2[b,c,d+od-3,h+oh-3,w+ow-3] (zero-pad OOB)

#define NB 2
#define NC 32
#define ND 32
#define NH 32
#define NW 32
#define HTILE 4
#define WTILE 8
#define NTHREADS 128
#define NCOMPUTE 112          // 4 wg * 7 ph * 4 hr

#define S2H 10                // HTILE + 6 halo rows
#define S2W 44                // 38 valid (w-3..34) padded to 44 (conflict-free: 44*dsh mod 8 == 4)
#define S2_SIZE (NC * S2H * S2W)        // 14080 floats
#define S1_STRIDE_HR 1044               // 1024 + 20 pad (hr-delta lands 20 banks over: mod 8 == 4)
#define S1_SIZE (HTILE * S1_STRIDE_HR)  // 4176 floats
#define SMEM_BYTES ((S2_SIZE + S1_SIZE) * 4)   // 73024 B

__device__ __forceinline__ void stcs4(float* p, float x, float y, float z, float w) {
    asm volatile("st.global.cs.v4.f32 [%0], {%1, %2, %3, %4};"
                 :: "l"(p), "f"(x), "f"(y), "f"(z), "f"(w) : "memory");
}

__global__ __launch_bounds__(NTHREADS) void corr3d_kernel(
    const float* __restrict__ in1,
    const float* __restrict__ in2,
    float* __restrict__ out)
{
    extern __shared__ float smem[];
    float* s2 = smem;             // [c][sh][ws]  sh = h'-h0+3 (0..9), ws = w'+3 (0..37, pad 44)
    float* s1 = smem + S2_SIZE;   // [hr][c][w], hr stride S1_STRIDE_HR

    const int tid = threadIdx.x;
    const int h0  = blockIdx.x * HTILE;
    const int d   = blockIdx.y;
    const int b   = blockIdx.z;

    // Stage in1 rows for this (b, d, h-tile)
    for (int i = tid; i < HTILE * NC * NW; i += NTHREADS) {
        int w  = i & (NW - 1);
        int c  = (i >> 5) & (NC - 1);
        int hr = i >> 10;
        s1[hr * S1_STRIDE_HR + c * NW + w] =
            __ldg(&in1[(((size_t)b * NC + c) * ND + d) * (NH * NW) + (h0 + hr) * NW + w]);
    }

    // Compute mapping (tid < 112): wg = tid&3, ph = (tid>>2)%7, hr = tid/28
    const int wg = tid & 3;
    const int ph = (tid >> 2) % 7;
    const int hr = tid / 28;
    const int sh = hr + ph;        // slab h row (0..9)
    const int w0 = WTILE * wg;     // 0,8,16,24
    const bool is_compute = (tid < NCOMPUTE);

    #pragma unroll 1
    for (int od = 0; od < 7; ++od) {
        const int dp = d + od - 3;
        const bool dv = (dp >= 0) && (dp < ND);

        __syncthreads();   // prior iteration done before overwriting s2 (covers s1 on iter 0)

        // Load in2 slab [32][10][44], zero fill halo/OOB/pad
        for (int i = tid; i < S2_SIZE; i += NTHREADS) {
            int ws   = i % S2W;
            int rest = i / S2W;
            int shh  = rest % S2H;
            int c    = rest / S2H;
            int hp = h0 + shh - 3;
            int wp = ws - 3;
            float v = 0.0f;
            if (dv && hp >= 0 && hp < NH && wp >= 0 && wp < NW)
                v = __ldg(&in2[(((size_t)b * NC + c) * ND + dp) * (NH * NW) + hp * NW + wp]);
            s2[i] = v;
        }
        __syncthreads();

        if (is_compute) {
            float acc[7][WTILE];
            #pragma unroll
            for (int pw = 0; pw < 7; ++pw)
                #pragma unroll
                for (int k = 0; k < WTILE; ++k) acc[pw][k] = 0.0f;

            const float* s1p = &s1[hr * S1_STRIDE_HR + w0];
            const float* s2p = &s2[sh * S2W + w0];

            #pragma unroll 2
            for (int c = 0; c < NC; ++c) {
                float4 a0 = *reinterpret_cast<const float4*>(s1p + c * NW);
                float4 a1 = *reinterpret_cast<const float4*>(s1p + c * NW + 4);
                const float* p = s2p + c * (S2H * S2W);
                float4 v0 = *reinterpret_cast<const float4*>(p);
                float4 v1 = *reinterpret_cast<const float4*>(p + 4);
                float4 v2 = *reinterpret_cast<const float4*>(p + 8);
                float4 v3 = *reinterpret_cast<const float4*>(p + 12);
                float win[16] = {v0.x, v0.y, v0.z, v0.w,
                                 v1.x, v1.y, v1.z, v1.w,
                                 v2.x, v2.y, v2.z, v2.w,
                                 v3.x, v3.y, v3.z, v3.w};
                float a[WTILE] = {a0.x, a0.y, a0.z, a0.w, a1.x, a1.y, a1.z, a1.w};
                #pragma unroll
                for (int pw = 0; pw < 7; ++pw)
                    #pragma unroll
                    for (int k = 0; k < WTILE; ++k)
                        acc[pw][k] += a[k] * win[pw + k];
            }

            // Streaming stores: out[b, od, ph, pw, d, h0+hr, w0 .. w0+7]
            const int hq = h0 + hr;
            #pragma unroll
            for (int pw = 0; pw < 7; ++pw) {
                size_t off = ((size_t)(b * 343 + od * 49 + ph * 7 + pw) * ND + d) * (NH * NW)
                             + hq * NW + w0;
                stcs4(&out[off],     acc[pw][0], acc[pw][1], acc[pw][2], acc[pw][3]);
                stcs4(&out[off + 4], acc[pw][4], acc[pw][5], acc[pw][6], acc[pw][7]);
            }
        }
    }
}

extern "C" void kernel_launch(void* const* d_in, const int* in_sizes, int n_in,
                              void* d_out, int out_size) {
    const float* in1 = (const float*)d_in[0];
    const float* in2 = (const float*)d_in[1];
    float* out = (float*)d_out;

    cudaFuncSetAttribute(corr3d_kernel,
                         cudaFuncAttributeMaxDynamicSharedMemorySize, SMEM_BYTES);

    dim3 grid(NH / HTILE, ND, NB);   // (8, 32, 2) = 512 blocks
    corr3d_kernel<<<grid, NTHREADS, SMEM_BYTES>>>(in1, in2, out);
}

// round 4
// speedup vs baseline: 2.1672x; 2.1672x over previous
#include <cuda_runtime.h>
#include <cstddef>

// in1,in2: [B=2, C=32, D=32, H=32, W=32] fp32
// out:     [B, 7,7,7, D, H, W] fp32
// out[b,od,oh,ow,d,h,w] = sum_c in1[b,c,d,h,w]*in2[b,c,d+od-3,h+oh-3,w+ow-3] (zero-pad OOB)
//
// One block = (b, od, d, h-tile of 4). Grid 8 x 32 x 14 = 3584 blocks.
// Slab s2[c][sh][44] loaded via cp.async (rows are contiguous 128B in gmem),
// halo zero-filled by disjoint STS before the copies land. Left pad = 4 floats
// so every cp.async destination is 16B-aligned (ws = wp + 4).

#define NB 2
#define NC 32
#define ND 32
#define NH 32
#define NW 32
#define HTILE 4
#define WTILE 8
#define NTHREADS 128
#define NCOMPUTE 112          // 4 wg * 7 ph * 4 hr

#define S2H 10                // HTILE + 6 halo rows
#define S2W 44                // 4 left pad + 32 valid + 8 right pad (conflict-free mod-8 = 4)
#define S2_ROWS (NC * S2H)            // 320
#define S2_SIZE (S2_ROWS * S2W)       // 14080 floats
#define S1_STRIDE_HR 1044             // 1024 + 20 pad (20 mod 8 == 4 -> conflict-free)
#define S1_SIZE (HTILE * S1_STRIDE_HR)
#define SMEM_BYTES ((S2_SIZE + S1_SIZE) * 4)   // 73024 B -> 3 CTAs/SM

__device__ __forceinline__ void cpasync16(float* dst_smem, const float* src) {
    unsigned sdst = (unsigned)__cvta_generic_to_shared(dst_smem);
    asm volatile("cp.async.cg.shared.global [%0], [%1], 16;" :: "r"(sdst), "l"(src));
}

__device__ __forceinline__ void stcs4(float* p, float x, float y, float z, float w) {
    asm volatile("st.global.cs.v4.f32 [%0], {%1, %2, %3, %4};"
                 :: "l"(p), "f"(x), "f"(y), "f"(z), "f"(w) : "memory");
}

__global__ __launch_bounds__(NTHREADS) void corr3d_kernel(
    const float* __restrict__ in1,
    const float* __restrict__ in2,
    float* __restrict__ out)
{
    extern __shared__ float smem[];
    float* s2 = smem;             // [c*10+sh][44]
    float* s1 = smem + S2_SIZE;   // [hr][c][32], hr stride 1044

    const int tid = threadIdx.x;
    const int h0  = blockIdx.x * HTILE;
    const int d   = blockIdx.y;
    const int b   = blockIdx.z / 7;
    const int od  = blockIdx.z % 7;
    const int dp  = d + od - 3;
    const bool dv = (dp >= 0) && (dp < ND);

    // Compute mapping (tid < 112): wg = tid&3, ph = (tid>>2)%7, hr = tid/28
    const int wg = tid & 3;
    const int ph = (tid >> 2) % 7;
    const int hr = tid / 28;
    const int sh = hr + ph;        // slab h row (0..9)
    const int w0 = WTILE * wg;     // 0,8,16,24
    const bool is_compute = (tid < NCOMPUTE);

    if (dv) {
        // --- Halo zero-fill (disjoint from cp.async targets) ---
        const float4 z4 = make_float4(0.f, 0.f, 0.f, 0.f);
        #pragma unroll
        for (int r = tid; r < S2_ROWS; r += NTHREADS) {
            int shh = r % S2H;
            int hp  = h0 + shh - 3;
            float4* row = reinterpret_cast<float4*>(s2 + r * S2W);
            row[0]  = z4;   // ws 0..3   (wp -4..-1)
            row[9]  = z4;   // ws 36..39 (wp 32..35)
            row[10] = z4;   // ws 40..43
            if (hp < 0 || hp >= NH) {
                #pragma unroll
                for (int q = 1; q < 9; ++q) row[q] = z4;   // full row zero
            }
        }

        // --- Async copies: s2 valid rows (128B each) ---
        const size_t base2 = ((size_t)b * NC * ND + dp) * (NH * NW);  // + c*ND*NH*NW + hp*NW
        #pragma unroll
        for (int r = tid; r < S2_ROWS; r += NTHREADS) {
            int c   = r / S2H;
            int shh = r % S2H;
            int hp  = h0 + shh - 3;
            if (hp >= 0 && hp < NH) {
                const float* src = in2 + base2 + (size_t)c * (ND * NH * NW) + hp * NW;
                float* dst = s2 + r * S2W + 4;
                #pragma unroll
                for (int q = 0; q < 8; ++q) cpasync16(dst + q * 4, src + q * 4);
            }
        }

        // --- Async copies: s1 rows (one 128B row per thread) ---
        {
            int c  = tid & 31;
            int h1 = tid >> 5;     // hr
            const float* src = in1 + ((size_t)(b * NC + c) * ND + d) * (NH * NW) + (h0 + h1) * NW;
            float* dst = s1 + h1 * S1_STRIDE_HR + c * NW;
            #pragma unroll
            for (int q = 0; q < 8; ++q) cpasync16(dst + q * 4, src + q * 4);
        }

        asm volatile("cp.async.commit_group;" ::: "memory");
        asm volatile("cp.async.wait_group 0;" ::: "memory");
        __syncthreads();
    }

    if (is_compute) {
        float acc[7][WTILE];
        #pragma unroll
        for (int pw = 0; pw < 7; ++pw)
            #pragma unroll
            for (int k = 0; k < WTILE; ++k) acc[pw][k] = 0.0f;

        if (dv) {
            const float* s1p = &s1[hr * S1_STRIDE_HR + w0];
            const float* s2p = &s2[sh * S2W + w0];   // + c * (S2H*S2W)

            #pragma unroll 2
            for (int c = 0; c < NC; ++c) {
                float4 a0 = *reinterpret_cast<const float4*>(s1p + c * NW);
                float4 a1 = *reinterpret_cast<const float4*>(s1p + c * NW + 4);
                const float* p = s2p + c * (S2H * S2W);
                float4 v0 = *reinterpret_cast<const float4*>(p);
                float4 v1 = *reinterpret_cast<const float4*>(p + 4);
                float4 v2 = *reinterpret_cast<const float4*>(p + 8);
                float4 v3 = *reinterpret_cast<const float4*>(p + 12);
                float win[16] = {v0.x, v0.y, v0.z, v0.w,
                                 v1.x, v1.y, v1.z, v1.w,
                                 v2.x, v2.y, v2.z, v2.w,
                                 v3.x, v3.y, v3.z, v3.w};
                float a[WTILE] = {a0.x, a0.y, a0.z, a0.w, a1.x, a1.y, a1.z, a1.w};
                // output w = w0+k uses wp = w0+k+pw-3 -> ws = w0+k+pw+1 -> win[k+pw+1]
                #pragma unroll
                for (int pw = 0; pw < 7; ++pw)
                    #pragma unroll
                    for (int k = 0; k < WTILE; ++k)
                        acc[pw][k] += a[k] * win[pw + k + 1];
            }
        }

        // Streaming stores: out[b, od, ph, pw, d, h0+hr, w0 .. w0+7]
        const int hq = h0 + hr;
        #pragma unroll
        for (int pw = 0; pw < 7; ++pw) {
            size_t off = ((size_t)(b * 343 + od * 49 + ph * 7 + pw) * ND + d) * (NH * NW)
                         + hq * NW + w0;
            stcs4(&out[off],     acc[pw][0], acc[pw][1], acc[pw][2], acc[pw][3]);
            stcs4(&out[off + 4], acc[pw][4], acc[pw][5], acc[pw][6], acc[pw][7]);
        }
    }
}

extern "C" void kernel_launch(void* const* d_in, const int* in_sizes, int n_in,
                              void* d_out, int out_size) {
    const float* in1 = (const float*)d_in[0];
    const float* in2 = (const float*)d_in[1];
    float* out = (float*)d_out;

    cudaFuncSetAttribute(corr3d_kernel,
                         cudaFuncAttributeMaxDynamicSharedMemorySize, SMEM_BYTES);

    dim3 grid(NH / HTILE, ND, NB * 7);   // (8, 32, 14) = 3584 blocks, one od each
    corr3d_kernel<<<grid, NTHREADS, SMEM_BYTES>>>(in1, in2, out);
}